// round 1
// baseline (speedup 1.0000x reference)
#include <cuda_runtime.h>
#include <math_constants.h>

#define BH      16
#define LQ      4096
#define DD      64
#define SK      45
#define UU      45
#define NSPLIT  32
#define SPLIT_KEYS 128
#define NCHUNK  32
#define CHUNK   128

// ---------------- scratch (device globals; no allocation allowed) ----------
__device__ __align__(16) float g_M[BH * LQ];
__device__ __align__(16) int   g_top[BH * UU];
__device__ __align__(16) float g_pm[BH * UU * NSPLIT];
__device__ __align__(16) float g_pl[BH * UU * NSPLIT];
__device__ __align__(16) float g_pacc[BH * UU * NSPLIT * DD];
__device__ __align__(16) float g_chunk[BH * NCHUNK * DD];

// ---------------- Stage 1: sparsity measure M ------------------------------
// One warp per (bh, q). Lane s handles sample s (and s+32 for s<13):
// full 64-dim dot via 16 LDG.128 per lane; q broadcast from smem via LDS.128.
__global__ __launch_bounds__(256) void k_M(const float* __restrict__ Q,
                                           const float* __restrict__ K,
                                           const int*   __restrict__ idx)
{
    __shared__ __align__(16) float qs[8][64];
    __shared__ int sidx[8][48];
    int w = threadIdx.x >> 5, lane = threadIdx.x & 31;
    int gw = blockIdx.x * 8 + w;
    int bh = gw >> 12, q = gw & (LQ - 1);
    const float* Kb = K + (size_t)bh * (LQ * DD);

    float2 qv2 = *(const float2*)(Q + ((size_t)bh * LQ + q) * DD + 2 * lane);
    qs[w][2 * lane] = qv2.x; qs[w][2 * lane + 1] = qv2.y;
    sidx[w][lane] = idx[q * SK + lane];
    if (lane < SK - 32) sidx[w][32 + lane] = idx[q * SK + 32 + lane];
    __syncwarp();

    const float4* qp4 = (const float4*)qs[w];
    float mx, sm;
    {
        const float4* kp = (const float4*)(Kb + (size_t)sidx[w][lane] * DD);
        float d0 = 0.f, d1 = 0.f, d2 = 0.f, d3 = 0.f;
#pragma unroll
        for (int i = 0; i < 16; i++) {
            float4 kv = __ldg(kp + i);
            float4 qq = qp4[i];
            d0 = fmaf(kv.x, qq.x, d0); d1 = fmaf(kv.y, qq.y, d1);
            d2 = fmaf(kv.z, qq.z, d2); d3 = fmaf(kv.w, qq.w, d3);
        }
        float dot = (d0 + d1) + (d2 + d3);
        mx = dot; sm = dot;
    }
    if (lane < SK - 32) {
        const float4* kp = (const float4*)(Kb + (size_t)sidx[w][32 + lane] * DD);
        float d0 = 0.f, d1 = 0.f, d2 = 0.f, d3 = 0.f;
#pragma unroll
        for (int i = 0; i < 16; i++) {
            float4 kv = __ldg(kp + i);
            float4 qq = qp4[i];
            d0 = fmaf(kv.x, qq.x, d0); d1 = fmaf(kv.y, qq.y, d1);
            d2 = fmaf(kv.z, qq.z, d2); d3 = fmaf(kv.w, qq.w, d3);
        }
        float dot = (d0 + d1) + (d2 + d3);
        mx = fmaxf(mx, dot); sm += dot;
    }
#pragma unroll
    for (int o = 16; o > 0; o >>= 1) {
        mx = fmaxf(mx, __shfl_xor_sync(0xffffffffu, mx, o));
        sm += __shfl_xor_sync(0xffffffffu, sm, o);
    }
    if (lane == 0) g_M[gw] = mx - sm * (1.0f / (float)LQ);
}

// ---------------- Stage 2: top-45 per (b,h) --------------------------------
__global__ __launch_bounds__(256) void k_top()
{
    __shared__ float sv[LQ];           // 16 KB
    __shared__ float rmax[256];
    __shared__ int   ridx[256];
    int bh = blockIdx.x, t = threadIdx.x;
    for (int i = t; i < LQ; i += 256) sv[i] = g_M[bh * LQ + i];
    __syncthreads();
    for (int it = 0; it < UU; it++) {
        float bm = -CUDART_INF_F; int bi = 0;
        for (int i = t; i < LQ; i += 256) {
            float v = sv[i];
            if (v > bm) { bm = v; bi = i; }
        }
        rmax[t] = bm; ridx[t] = bi;
        __syncthreads();
        for (int s = 128; s > 0; s >>= 1) {
            if (t < s && rmax[t + s] > rmax[t]) { rmax[t] = rmax[t + s]; ridx[t] = ridx[t + s]; }
            __syncthreads();
        }
        if (t == 0) { g_top[bh * UU + it] = ridx[0]; sv[ridx[0]] = -CUDART_INF_F; }
        __syncthreads();
    }
}

// ---------------- Stage 3: split-KV flash attention for selected rows ------
// grid (NSPLIT, BH), block 256 (8 warps). Warp w owns u = w, w+8, ... (<=6 u's).
// Online softmax partials (m, l, acc[64]) per u per split; combined later.
__global__ __launch_bounds__(256) void k_attn(const float* __restrict__ Q,
                                              const float* __restrict__ K,
                                              const float* __restrict__ V)
{
    __shared__ __align__(16) float Qs[UU][DD];   // 11.25 KB (pre-scaled)
    __shared__ __align__(16) float Kt[DD][66];   // transposed, padded: 16.5 KB
    __shared__ __align__(16) float Vs[64][DD];   // 16 KB
    __shared__ int tops[UU];
    __shared__ int s_maxtop;

    int split = blockIdx.x, bh = blockIdx.y;
    int t = threadIdx.x, w = t >> 5, lane = t & 31;

    if (t < UU) tops[t] = g_top[bh * UU + t];
    __syncthreads();
    const float scale = 0.125f;   // 1/sqrt(64)
    for (int r = w; r < UU; r += 8) {
        float2 v = *(const float2*)(Q + ((size_t)bh * LQ + tops[r]) * DD + 2 * lane);
        Qs[r][2 * lane]     = v.x * scale;
        Qs[r][2 * lane + 1] = v.y * scale;
    }
    if (t == 0) {
        int m = 0;
        for (int i = 0; i < UU; i++) m = max(m, tops[i]);
        s_maxtop = m;
    }

    float mx[6], l[6]; float2 acc[6];
#pragma unroll
    for (int j = 0; j < 6; j++) { mx[j] = -CUDART_INF_F; l[j] = 0.f; acc[j] = make_float2(0.f, 0.f); }
    __syncthreads();

    int k0 = split * SPLIT_KEYS;
    for (int sub = 0; sub < SPLIT_KEYS / 64; sub++) {
        int kb = k0 + sub * 64;
        __syncthreads();                      // prev-iteration readers done
        if (kb <= s_maxtop) {
            for (int i = t; i < 64 * DD; i += 256) {
                int kk = i >> 6, d = i & 63;
                float kvv = K[((size_t)bh * LQ + kb + kk) * DD + d];
                float vvv = V[((size_t)bh * LQ + kb + kk) * DD + d];
                Kt[d][kk] = kvv;
                Vs[kk][d] = vvv;
            }
        }
        __syncthreads();

        bool act[6]; bool any = false;
#pragma unroll
        for (int j = 0; j < 6; j++) {
            int u = w + 8 * j;
            act[j] = (u < UU) && (kb <= tops[u]);
            any |= act[j];
        }
        if (!any) continue;

        // scores: lane owns keys 2*lane, 2*lane+1 of the subtile
        float s0[6], s1[6];
#pragma unroll
        for (int j = 0; j < 6; j++) { s0[j] = 0.f; s1[j] = 0.f; }
#pragma unroll 16
        for (int d = 0; d < DD; d++) {
            float2 kt = *(const float2*)&Kt[d][2 * lane];
#pragma unroll
            for (int j = 0; j < 6; j++) {
                int u = w + 8 * j;
                if (u < UU) {
                    float qv = Qs[u][d];
                    s0[j] = fmaf(qv, kt.x, s0[j]);
                    s1[j] = fmaf(qv, kt.y, s1[j]);
                }
            }
        }

        float2 e2[6];
        int kk0 = kb + 2 * lane;
#pragma unroll
        for (int j = 0; j < 6; j++) {
            e2[j] = make_float2(0.f, 0.f);
            if (!act[j]) continue;            // warp-uniform
            int mu = tops[w + 8 * j];
            float a = (kk0     <= mu) ? s0[j] : -CUDART_INF_F;
            float b = (kk0 + 1 <= mu) ? s1[j] : -CUDART_INF_F;
            float lm = fmaxf(a, b);
#pragma unroll
            for (int o = 16; o > 0; o >>= 1) lm = fmaxf(lm, __shfl_xor_sync(0xffffffffu, lm, o));
            float nm   = fmaxf(mx[j], lm);
            float corr = __expf(mx[j] - nm);
            float ea = __expf(a - nm);
            float eb = __expf(b - nm);
            float ts = ea + eb;
#pragma unroll
            for (int o = 16; o > 0; o >>= 1) ts += __shfl_xor_sync(0xffffffffu, ts, o);
            mx[j] = nm;
            l[j]  = l[j] * corr + ts;
            acc[j].x *= corr; acc[j].y *= corr;
            e2[j].x = ea; e2[j].y = eb;
        }

        // AV: lane owns d = 2*lane, 2*lane+1; weights broadcast via shfl
#pragma unroll 8
        for (int kk = 0; kk < 64; kk++) {
            float2 vv = *(const float2*)&Vs[kk][2 * lane];
#pragma unroll
            for (int j = 0; j < 6; j++) {
                if (act[j]) {                 // warp-uniform
                    float ek = __shfl_sync(0xffffffffu, (kk & 1) ? e2[j].y : e2[j].x, kk >> 1);
                    acc[j].x = fmaf(ek, vv.x, acc[j].x);
                    acc[j].y = fmaf(ek, vv.y, acc[j].y);
                }
            }
        }
    }

    // write partials (always — combine relies on valid m/l)
#pragma unroll
    for (int j = 0; j < 6; j++) {
        int u = w + 8 * j;
        if (u >= UU) continue;               // warp-uniform
        int pb = (bh * UU + u) * NSPLIT + split;
        *(float2*)&g_pacc[(size_t)pb * DD + 2 * lane] = acc[j];
        if (lane == 0) { g_pm[pb] = mx[j]; g_pl[pb] = l[j]; }
    }
}

// ---------------- Stage 5b: combine split partials into selected rows ------
__global__ __launch_bounds__(64) void k_comb(float* __restrict__ out)
{
    int g  = blockIdx.x;                    // bh*UU + u
    int bh = g / UU;
    int d  = threadIdx.x;
    float mg = -CUDART_INF_F;
#pragma unroll 4
    for (int i = 0; i < NSPLIT; i++) mg = fmaxf(mg, g_pm[g * NSPLIT + i]);
    float os = 0.f, ls = 0.f;
    for (int i = 0; i < NSPLIT; i++) {
        float wgt = __expf(g_pm[g * NSPLIT + i] - mg);
        ls = fmaf(wgt, g_pl[g * NSPLIT + i], ls);
        os = fmaf(wgt, g_pacc[(size_t)(g * NSPLIT + i) * DD + d], os);
    }
    int row = g_top[g];
    out[((size_t)bh * LQ + row) * DD + d] = os / ls;
}

// ---------------- Stage 4: cumsum(V) along L, 3 phases ---------------------
__global__ __launch_bounds__(256) void k_csumA(const float* __restrict__ V)
{
    int c = blockIdx.x, bh = blockIdx.y;
    int t = threadIdx.x, d = t & 63, r = t >> 6;
    __shared__ float sred[4][64];
    float acc = 0.f;
    const float* base = V + ((size_t)bh * LQ + c * CHUNK) * DD;
#pragma unroll 4
    for (int i = 0; i < CHUNK / 4; i++) acc += base[(i * 4 + r) * DD + d];
    sred[r][d] = acc;
    __syncthreads();
    if (r == 0)
        g_chunk[(bh * NCHUNK + c) * DD + d] = sred[0][d] + sred[1][d] + sred[2][d] + sred[3][d];
}

__global__ __launch_bounds__(1024) void k_csumB()
{
    int t = threadIdx.x;                    // 1024 = BH * DD
    int bh = t >> 6, d = t & 63;
    float run = 0.f;
    for (int c = 0; c < NCHUNK; c++) {
        int a = (bh * NCHUNK + c) * DD + d;
        float v = g_chunk[a];
        g_chunk[a] = run;                   // exclusive prefix, in place
        run += v;
    }
}

__global__ __launch_bounds__(512) void k_csumC(const float* __restrict__ V,
                                               float* __restrict__ out)
{
    __shared__ float tile[CHUNK * DD];      // 32 KB
    __shared__ float soff[DD];
    int c = blockIdx.x, bh = blockIdx.y;
    int t = threadIdx.x;
    const float* base = V + ((size_t)bh * LQ + c * CHUNK) * DD;
#pragma unroll
    for (int i = 0; i < 16; i++) tile[t + 512 * i] = base[t + 512 * i];
    if (t < DD) soff[t] = g_chunk[(bh * NCHUNK + c) * DD + t];
    __syncthreads();
#pragma unroll
    for (int s = 1; s < CHUNK; s <<= 1) {
        float tmp[16];
#pragma unroll
        for (int i = 0; i < 16; i++) {
            int e = t + 512 * i;
            int lrow = e >> 6;
            tmp[i] = (lrow >= s) ? tile[e - s * DD] : 0.f;
        }
        __syncthreads();
#pragma unroll
        for (int i = 0; i < 16; i++) tile[t + 512 * i] += tmp[i];
        __syncthreads();
    }
    float* ob = out + ((size_t)bh * LQ + c * CHUNK) * DD;
#pragma unroll
    for (int i = 0; i < 16; i++) {
        int e = t + 512 * i;
        ob[e] = tile[e] + soff[e & 63];
    }
}

// ---------------- launcher --------------------------------------------------
extern "C" void kernel_launch(void* const* d_in, const int* in_sizes, int n_in,
                              void* d_out, int out_size)
{
    (void)in_sizes; (void)n_in; (void)out_size;
    const float* Q   = (const float*)d_in[0];
    const float* K   = (const float*)d_in[1];
    const float* V   = (const float*)d_in[2];
    const int*   idx = (const int*)d_in[3];
    float* out = (float*)d_out;

    k_M<<<BH * LQ / 8, 256>>>(Q, K, idx);
    k_top<<<BH, 256>>>();
    k_csumA<<<dim3(NCHUNK, BH), 256>>>(V);
    k_csumB<<<1, 1024>>>();
    k_csumC<<<dim3(NCHUNK, BH), 512>>>(V, out);
    k_attn<<<dim3(NSPLIT, BH), 256>>>(Q, K, V);
    k_comb<<<BH * UU, 64>>>(out);
}

// round 2
// speedup vs baseline: 1.6418x; 1.6418x over previous
#include <cuda_runtime.h>
#include <math_constants.h>

#define BH      16
#define LQ      4096
#define DD      64
#define SK      45
#define UU      45
#define NSPLIT  32
#define SPLIT_KEYS 128
#define NCHUNK  32
#define CHUNK   128

// ---------------- scratch (device globals; no allocation allowed) ----------
__device__ __align__(16) float g_M[BH * LQ];
__device__ __align__(16) int   g_top[BH * UU];
__device__ __align__(16) float g_pm[BH * UU * NSPLIT];
__device__ __align__(16) float g_pl[BH * UU * NSPLIT];
__device__ __align__(16) float g_pacc[BH * UU * NSPLIT * DD];
__device__ __align__(16) float g_chunk[BH * NCHUNK * DD];

// ---------------- Stage 1: sparsity measure M ------------------------------
// One warp per (bh,q). 8 lanes per sampled key row, 4 rows per LDG step:
// each LDG.128 warp instruction touches only 4-8 lines (vs 32 before).
__global__ __launch_bounds__(256) void k_M(const float* __restrict__ Q,
                                           const float* __restrict__ K,
                                           const int*   __restrict__ idx)
{
    __shared__ int sidx[8][48];
    int w = threadIdx.x >> 5, lane = threadIdx.x & 31;
    int gw = blockIdx.x * 8 + w;
    int bh = gw >> 12, q = gw & (LQ - 1);
    const float4* Kb4 = (const float4*)(K + (size_t)bh * (LQ * DD));

    sidx[w][lane] = idx[q * SK + lane];
    if (lane < SK - 32) sidx[w][32 + lane] = idx[q * SK + 32 + lane];
    if (lane >= 29)     sidx[w][16 + lane] = idx[q * SK + SK - 1];  // pad 45..47
    __syncwarp();

    int r = lane >> 3, c = lane & 7;   // r: row-in-group, c: 8-float column slot
    const float4* Qr4 = (const float4*)(Q + ((size_t)bh * LQ + q) * DD);
    float4 qa = Qr4[2 * c], qb = Qr4[2 * c + 1];

    float mx = -CUDART_INF_F, sm = 0.f;
#pragma unroll 4
    for (int t = 0; t < 12; t++) {
        int s = 4 * t + r;
        int row = sidx[w][s];
        const float4* kp = Kb4 + (size_t)row * 16 + 2 * c;
        float4 ka = __ldg(kp);
        float4 kb = __ldg(kp + 1);
        float d;
        d = ka.x * qa.x;
        d = fmaf(ka.y, qa.y, d);
        d = fmaf(ka.z, qa.z, d);
        d = fmaf(ka.w, qa.w, d);
        d = fmaf(kb.x, qb.x, d);
        d = fmaf(kb.y, qb.y, d);
        d = fmaf(kb.z, qb.z, d);
        d = fmaf(kb.w, qb.w, d);
        d += __shfl_xor_sync(0xffffffffu, d, 1);
        d += __shfl_xor_sync(0xffffffffu, d, 2);
        d += __shfl_xor_sync(0xffffffffu, d, 4);
        if (s < SK) { mx = fmaxf(mx, d); sm += d; }
    }
    mx = fmaxf(mx, __shfl_xor_sync(0xffffffffu, mx, 8));
    sm +=          __shfl_xor_sync(0xffffffffu, sm, 8);
    mx = fmaxf(mx, __shfl_xor_sync(0xffffffffu, mx, 16));
    sm +=          __shfl_xor_sync(0xffffffffu, sm, 16);
    if (lane == 0) g_M[gw] = mx - sm * (1.0f / (float)LQ);
}

// ---------------- Stage 2: top-45 per (b,h) --------------------------------
// Phase 1: each warp selects top-45 of its 512-slice (shfl argmax, no block
// barriers). Phase 2: warp 0 merges the 8*45=360 candidates.
__global__ __launch_bounds__(256) void k_top()
{
    __shared__ float sv[LQ];            // 16 KB
    __shared__ float cval[8 * UU];
    __shared__ int   cidx[8 * UU];
    int bh = blockIdx.x, t = threadIdx.x, w = t >> 5, lane = t & 31;

    for (int i = t; i < LQ; i += 256) sv[i] = g_M[bh * LQ + i];
    __syncthreads();

    int base = w * 512;
    for (int it = 0; it < UU; it++) {
        float bv = -CUDART_INF_F; int bi = 0x7fffffff;
#pragma unroll
        for (int k = 0; k < 16; k++) {
            int i = base + lane + 32 * k;
            float v = sv[i];
            if (v > bv) { bv = v; bi = i; }        // ascending i: > keeps lowest
        }
#pragma unroll
        for (int off = 16; off > 0; off >>= 1) {
            float ov = __shfl_xor_sync(0xffffffffu, bv, off);
            int   oi = __shfl_xor_sync(0xffffffffu, bi, off);
            if (ov > bv || (ov == bv && oi < bi)) { bv = ov; bi = oi; }
        }
        if (lane == 0) { cval[w * UU + it] = bv; cidx[w * UU + it] = bi; sv[bi] = -CUDART_INF_F; }
        __syncwarp();
    }
    __syncthreads();

    if (w == 0) {
        for (int it = 0; it < UU; it++) {
            float bv = -CUDART_INF_F; int bi = 0x7fffffff, bs = 0;
#pragma unroll
            for (int k = 0; k < 12; k++) {
                int s = lane + 32 * k;
                if (s < 8 * UU) {
                    float v = cval[s]; int i = cidx[s];
                    if (v > bv || (v == bv && i < bi)) { bv = v; bi = i; bs = s; }
                }
            }
#pragma unroll
            for (int off = 16; off > 0; off >>= 1) {
                float ov = __shfl_xor_sync(0xffffffffu, bv, off);
                int   oi = __shfl_xor_sync(0xffffffffu, bi, off);
                int   os = __shfl_xor_sync(0xffffffffu, bs, off);
                if (ov > bv || (ov == bv && oi < bi)) { bv = ov; bi = oi; bs = os; }
            }
            if (lane == 0) { g_top[bh * UU + it] = bi; cval[bs] = -CUDART_INF_F; }
            __syncwarp();
        }
    }
}

// ---------------- Stage 3: split-KV flash attention for selected rows ------
__global__ __launch_bounds__(256) void k_attn(const float* __restrict__ Q,
                                              const float* __restrict__ K,
                                              const float* __restrict__ V)
{
    __shared__ __align__(16) float Qs[UU][DD];
    __shared__ __align__(16) float Kt[DD][66];
    __shared__ __align__(16) float Vs[64][DD];
    __shared__ int tops[UU];
    __shared__ int s_maxtop;

    int split = blockIdx.x, bh = blockIdx.y;
    int t = threadIdx.x, w = t >> 5, lane = t & 31;

    if (t < UU) tops[t] = g_top[bh * UU + t];
    __syncthreads();
    const float scale = 0.125f;
    for (int r = w; r < UU; r += 8) {
        float2 v = *(const float2*)(Q + ((size_t)bh * LQ + tops[r]) * DD + 2 * lane);
        Qs[r][2 * lane]     = v.x * scale;
        Qs[r][2 * lane + 1] = v.y * scale;
    }
    if (t == 0) {
        int m = 0;
        for (int i = 0; i < UU; i++) m = max(m, tops[i]);
        s_maxtop = m;
    }

    float mx[6], l[6]; float2 acc[6];
#pragma unroll
    for (int j = 0; j < 6; j++) { mx[j] = -CUDART_INF_F; l[j] = 0.f; acc[j] = make_float2(0.f, 0.f); }
    __syncthreads();

    int k0 = split * SPLIT_KEYS;
    for (int sub = 0; sub < SPLIT_KEYS / 64; sub++) {
        int kb = k0 + sub * 64;
        __syncthreads();
        if (kb > s_maxtop) break;          // block-uniform
        for (int i = t; i < 64 * DD; i += 256) {
            int kk = i >> 6, d = i & 63;
            Kt[d][kk] = K[((size_t)bh * LQ + kb + kk) * DD + d];
            Vs[kk][d] = V[((size_t)bh * LQ + kb + kk) * DD + d];
        }
        __syncthreads();

        bool act[6]; bool any = false;
#pragma unroll
        for (int j = 0; j < 6; j++) {
            int u = w + 8 * j;
            act[j] = (u < UU) && (kb <= tops[u]);
            any |= act[j];
        }
        if (!any) continue;                // both barriers of this iter already done

        float s0[6], s1[6];
#pragma unroll
        for (int j = 0; j < 6; j++) { s0[j] = 0.f; s1[j] = 0.f; }
#pragma unroll 16
        for (int d = 0; d < DD; d++) {
            float2 kt = *(const float2*)&Kt[d][2 * lane];
#pragma unroll
            for (int j = 0; j < 6; j++) {
                int u = w + 8 * j;
                if (u < UU) {
                    float qv = Qs[u][d];
                    s0[j] = fmaf(qv, kt.x, s0[j]);
                    s1[j] = fmaf(qv, kt.y, s1[j]);
                }
            }
        }

        float2 e2[6];
        int kk0 = kb + 2 * lane;
#pragma unroll
        for (int j = 0; j < 6; j++) {
            e2[j] = make_float2(0.f, 0.f);
            if (!act[j]) continue;
            int mu = tops[w + 8 * j];
            float a = (kk0     <= mu) ? s0[j] : -CUDART_INF_F;
            float b = (kk0 + 1 <= mu) ? s1[j] : -CUDART_INF_F;
            float lm = fmaxf(a, b);
#pragma unroll
            for (int o = 16; o > 0; o >>= 1) lm = fmaxf(lm, __shfl_xor_sync(0xffffffffu, lm, o));
            float nm   = fmaxf(mx[j], lm);
            float corr = __expf(mx[j] - nm);
            float ea = __expf(a - nm);
            float eb = __expf(b - nm);
            float ts = ea + eb;
#pragma unroll
            for (int o = 16; o > 0; o >>= 1) ts += __shfl_xor_sync(0xffffffffu, ts, o);
            mx[j] = nm;
            l[j]  = l[j] * corr + ts;
            acc[j].x *= corr; acc[j].y *= corr;
            e2[j].x = ea; e2[j].y = eb;
        }

#pragma unroll 8
        for (int kk = 0; kk < 64; kk++) {
            float2 vv = *(const float2*)&Vs[kk][2 * lane];
#pragma unroll
            for (int j = 0; j < 6; j++) {
                if (act[j]) {
                    float ek = __shfl_sync(0xffffffffu, (kk & 1) ? e2[j].y : e2[j].x, kk >> 1);
                    acc[j].x = fmaf(ek, vv.x, acc[j].x);
                    acc[j].y = fmaf(ek, vv.y, acc[j].y);
                }
            }
        }
    }

#pragma unroll
    for (int j = 0; j < 6; j++) {
        int u = w + 8 * j;
        if (u >= UU) continue;
        int pb = (bh * UU + u) * NSPLIT + split;
        *(float2*)&g_pacc[(size_t)pb * DD + 2 * lane] = acc[j];
        if (lane == 0) { g_pm[pb] = mx[j]; g_pl[pb] = l[j]; }
    }
}

// ---------------- combine split partials into selected rows ----------------
__global__ __launch_bounds__(64) void k_comb(float* __restrict__ out)
{
    int g  = blockIdx.x;                    // bh*UU + u
    int bh = g / UU;
    int d  = threadIdx.x;
    float mg = -CUDART_INF_F;
#pragma unroll 4
    for (int i = 0; i < NSPLIT; i++) mg = fmaxf(mg, g_pm[g * NSPLIT + i]);
    float os = 0.f, ls = 0.f;
    for (int i = 0; i < NSPLIT; i++) {
        float wgt = __expf(g_pm[g * NSPLIT + i] - mg);
        ls = fmaf(wgt, g_pl[g * NSPLIT + i], ls);
        os = fmaf(wgt, g_pacc[(size_t)(g * NSPLIT + i) * DD + d], os);
    }
    int row = g_top[g];
    out[((size_t)bh * LQ + row) * DD + d] = os / ls;
}

// ---------------- cumsum(V) along L: chunk sums, then per-chunk scan -------
__global__ __launch_bounds__(256) void k_csumA(const float* __restrict__ V)
{
    int c = blockIdx.x, bh = blockIdx.y;
    int t = threadIdx.x, d = t & 63, r = t >> 6;
    __shared__ float sred[4][64];
    float acc = 0.f;
    const float* base = V + ((size_t)bh * LQ + c * CHUNK) * DD;
#pragma unroll 4
    for (int i = 0; i < CHUNK / 4; i++) acc += base[(i * 4 + r) * DD + d];
    sred[r][d] = acc;
    __syncthreads();
    if (r == 0)
        g_chunk[(bh * NCHUNK + c) * DD + d] = sred[0][d] + sred[1][d] + sred[2][d] + sred[3][d];
}

__global__ __launch_bounds__(512) void k_csumC(const float* __restrict__ V,
                                               float* __restrict__ out)
{
    __shared__ float tile[CHUNK * DD];      // 32 KB
    __shared__ float pred[8][64];
    __shared__ float soff[DD];
    int c = blockIdx.x, bh = blockIdx.y;
    int t = threadIdx.x;

    // exclusive prefix over preceding chunk sums (replaces old serial kernel)
    {
        int d = t & 63, g = t >> 6;         // 8 groups of 64
        float p = 0.f;
        for (int j = g; j < c; j += 8) p += g_chunk[(bh * NCHUNK + j) * DD + d];
        pred[g][d] = p;
    }
    const float* base = V + ((size_t)bh * LQ + c * CHUNK) * DD;
#pragma unroll
    for (int i = 0; i < 16; i++) tile[t + 512 * i] = base[t + 512 * i];
    __syncthreads();
    if (t < DD) {
        float s = 0.f;
#pragma unroll
        for (int g = 0; g < 8; g++) s += pred[g][t];
        soff[t] = s;
    }
    __syncthreads();
#pragma unroll
    for (int s = 1; s < CHUNK; s <<= 1) {
        float tmp[16];
#pragma unroll
        for (int i = 0; i < 16; i++) {
            int e = t + 512 * i;
            int lrow = e >> 6;
            tmp[i] = (lrow >= s) ? tile[e - s * DD] : 0.f;
        }
        __syncthreads();
#pragma unroll
        for (int i = 0; i < 16; i++) tile[t + 512 * i] += tmp[i];
        __syncthreads();
    }
    float* ob = out + ((size_t)bh * LQ + c * CHUNK) * DD;
#pragma unroll
    for (int i = 0; i < 16; i++) {
        int e = t + 512 * i;
        ob[e] = tile[e] + soff[e & 63];
    }
}

// ---------------- launcher --------------------------------------------------
extern "C" void kernel_launch(void* const* d_in, const int* in_sizes, int n_in,
                              void* d_out, int out_size)
{
    (void)in_sizes; (void)n_in; (void)out_size;
    const float* Q   = (const float*)d_in[0];
    const float* K   = (const float*)d_in[1];
    const float* V   = (const float*)d_in[2];
    const int*   idx = (const int*)d_in[3];
    float* out = (float*)d_out;

    k_M<<<BH * LQ / 8, 256>>>(Q, K, idx);
    k_top<<<BH, 256>>>();
    k_attn<<<dim3(NSPLIT, BH), 256>>>(Q, K, V);
    k_csumA<<<dim3(NCHUNK, BH), 256>>>(V);
    k_csumC<<<dim3(NCHUNK, BH), 512>>>(V, out);
    k_comb<<<BH * UU, 64>>>(out);
}

// round 5
// speedup vs baseline: 1.9286x; 1.1747x over previous
#include <cuda_runtime.h>
#include <math_constants.h>

#define BH      16
#define LQ      4096
#define DD      64
#define SK      45
#define UU      45
#define NSPLIT  32
#define SPLIT_KEYS 128
#define NCHUNK  32
#define CHUNK   128

// ---------------- scratch (device globals; no allocation allowed) ----------
__device__ __align__(16) float g_M[BH * LQ];
__device__ __align__(16) int   g_top[BH * UU];
__device__ __align__(16) float g_pm[BH * UU * NSPLIT];
__device__ __align__(16) float g_pl[BH * UU * NSPLIT];
__device__ __align__(16) float g_pacc[BH * UU * NSPLIT * DD];
__device__ __align__(16) float g_chunk[BH * NCHUNK * DD];

// ---------------- Stage 1: sparsity measure M ------------------------------
// One warp per (bh,q). 8 lanes per sampled key row, 4 rows per LDG step.
// Lane c reads contiguous bytes [16c,16c+16) of the FIRST half-row in ka and
// of the SECOND half-row in kb -> each LDG.128 = 4 fully-utilized 128B lines.
__global__ __launch_bounds__(256) void k_M(const float* __restrict__ Q,
                                           const float* __restrict__ K,
                                           const int*   __restrict__ idx)
{
    __shared__ int sidx[8][48];
    int w = threadIdx.x >> 5, lane = threadIdx.x & 31;
    int gw = blockIdx.x * 8 + w;
    int bh = gw >> 12, q = gw & (LQ - 1);
    const float4* Kb4 = (const float4*)(K + (size_t)bh * (LQ * DD));

    sidx[w][lane] = idx[q * SK + lane];
    if (lane < SK - 32) sidx[w][32 + lane] = idx[q * SK + 32 + lane];
    if (lane >= 29)     sidx[w][16 + lane] = idx[q * SK + SK - 1];  // pad 45..47
    __syncwarp();

    int r = lane >> 3, c = lane & 7;   // r: row-in-group, c: float4 slot
    const float4* Qr4 = (const float4*)(Q + ((size_t)bh * LQ + q) * DD);
    float4 qa = Qr4[c];        // first half of q row
    float4 qb = Qr4[c + 8];    // second half

    float mx = -CUDART_INF_F, sm = 0.f;
#pragma unroll 4
    for (int t = 0; t < 12; t++) {
        int s = 4 * t + r;
        int row = sidx[w][s];
        const float4* kp = Kb4 + (size_t)row * 16;
        float4 ka = __ldg(kp + c);        // bytes [16c,16c+16) of half 0
        float4 kb = __ldg(kp + c + 8);    // bytes [16c,16c+16) of half 1
        float d;
        d = ka.x * qa.x;
        d = fmaf(ka.y, qa.y, d);
        d = fmaf(ka.z, qa.z, d);
        d = fmaf(ka.w, qa.w, d);
        d = fmaf(kb.x, qb.x, d);
        d = fmaf(kb.y, qb.y, d);
        d = fmaf(kb.z, qb.z, d);
        d = fmaf(kb.w, qb.w, d);
        d += __shfl_xor_sync(0xffffffffu, d, 1);
        d += __shfl_xor_sync(0xffffffffu, d, 2);
        d += __shfl_xor_sync(0xffffffffu, d, 4);
        if (s < SK) { mx = fmaxf(mx, d); sm += d; }
    }
    mx = fmaxf(mx, __shfl_xor_sync(0xffffffffu, mx, 8));
    sm +=          __shfl_xor_sync(0xffffffffu, sm, 8);
    mx = fmaxf(mx, __shfl_xor_sync(0xffffffffu, mx, 16));
    sm +=          __shfl_xor_sync(0xffffffffu, sm, 16);
    if (lane == 0) g_M[gw] = mx - sm * (1.0f / (float)LQ);
}

// ---------------- Stage 2: top-45 per (b,h) --------------------------------
__global__ __launch_bounds__(256) void k_top()
{
    __shared__ float sv[LQ];            // 16 KB
    __shared__ float cval[8 * UU];
    __shared__ int   cidx[8 * UU];
    int bh = blockIdx.x, t = threadIdx.x, w = t >> 5, lane = t & 31;

    for (int i = t; i < LQ; i += 256) sv[i] = g_M[bh * LQ + i];
    __syncthreads();

    int base = w * 512;
    for (int it = 0; it < UU; it++) {
        float bv = -CUDART_INF_F; int bi = 0x7fffffff;
#pragma unroll
        for (int k = 0; k < 16; k++) {
            int i = base + lane + 32 * k;
            float v = sv[i];
            if (v > bv) { bv = v; bi = i; }
        }
#pragma unroll
        for (int off = 16; off > 0; off >>= 1) {
            float ov = __shfl_xor_sync(0xffffffffu, bv, off);
            int   oi = __shfl_xor_sync(0xffffffffu, bi, off);
            if (ov > bv || (ov == bv && oi < bi)) { bv = ov; bi = oi; }
        }
        if (lane == 0) { cval[w * UU + it] = bv; cidx[w * UU + it] = bi; sv[bi] = -CUDART_INF_F; }
        __syncwarp();
    }
    __syncthreads();

    if (w == 0) {
        for (int it = 0; it < UU; it++) {
            float bv = -CUDART_INF_F; int bi = 0x7fffffff, bs = 0;
#pragma unroll
            for (int k = 0; k < 12; k++) {
                int s = lane + 32 * k;
                if (s < 8 * UU) {
                    float v = cval[s]; int i = cidx[s];
                    if (v > bv || (v == bv && i < bi)) { bv = v; bi = i; bs = s; }
                }
            }
#pragma unroll
            for (int off = 16; off > 0; off >>= 1) {
                float ov = __shfl_xor_sync(0xffffffffu, bv, off);
                int   oi = __shfl_xor_sync(0xffffffffu, bi, off);
                int   os = __shfl_xor_sync(0xffffffffu, bs, off);
                if (ov > bv || (ov == bv && oi < bi)) { bv = ov; bi = oi; bs = os; }
            }
            if (lane == 0) { g_top[bh * UU + it] = bi; cval[bs] = -CUDART_INF_F; }
            __syncwarp();
        }
    }
}

// ---------------- Stage 3: split-KV flash attention for selected rows ------
__global__ __launch_bounds__(256) void k_attn(const float* __restrict__ Q,
                                              const float* __restrict__ K,
                                              const float* __restrict__ V)
{
    __shared__ __align__(16) float Qs[UU][DD];
    __shared__ __align__(16) float Kt[DD][66];
    __shared__ __align__(16) float Vs[64][DD];
    __shared__ int tops[UU];
    __shared__ int s_maxtop;

    int split = blockIdx.x, bh = blockIdx.y;
    int t = threadIdx.x, w = t >> 5, lane = t & 31;

    if (t < UU) tops[t] = g_top[bh * UU + t];
    __syncthreads();
    const float scale = 0.125f;
    for (int r = w; r < UU; r += 8) {
        float2 v = *(const float2*)(Q + ((size_t)bh * LQ + tops[r]) * DD + 2 * lane);
        Qs[r][2 * lane]     = v.x * scale;
        Qs[r][2 * lane + 1] = v.y * scale;
    }
    if (t == 0) {
        int m = 0;
        for (int i = 0; i < UU; i++) m = max(m, tops[i]);
        s_maxtop = m;
    }

    float mx[6], l[6]; float2 acc[6];
#pragma unroll
    for (int j = 0; j < 6; j++) { mx[j] = -CUDART_INF_F; l[j] = 0.f; acc[j] = make_float2(0.f, 0.f); }
    __syncthreads();

    int k0 = split * SPLIT_KEYS;
    for (int sub = 0; sub < SPLIT_KEYS / 64; sub++) {
        int kb = k0 + sub * 64;
        __syncthreads();
        if (kb > s_maxtop) break;
        for (int i = t; i < 64 * DD; i += 256) {
            int kk = i >> 6, d = i & 63;
            Kt[d][kk] = K[((size_t)bh * LQ + kb + kk) * DD + d];
            Vs[kk][d] = V[((size_t)bh * LQ + kb + kk) * DD + d];
        }
        __syncthreads();

        bool act[6]; bool any = false;
#pragma unroll
        for (int j = 0; j < 6; j++) {
            int u = w + 8 * j;
            act[j] = (u < UU) && (kb <= tops[u]);
            any |= act[j];
        }
        if (!any) continue;

        float s0[6], s1[6];
#pragma unroll
        for (int j = 0; j < 6; j++) { s0[j] = 0.f; s1[j] = 0.f; }
#pragma unroll 16
        for (int d = 0; d < DD; d++) {
            float2 kt = *(const float2*)&Kt[d][2 * lane];
#pragma unroll
            for (int j = 0; j < 6; j++) {
                int u = w + 8 * j;
                if (u < UU) {
                    float qv = Qs[u][d];
                    s0[j] = fmaf(qv, kt.x, s0[j]);
                    s1[j] = fmaf(qv, kt.y, s1[j]);
                }
            }
        }

        float2 e2[6];
        int kk0 = kb + 2 * lane;
#pragma unroll
        for (int j = 0; j < 6; j++) {
            e2[j] = make_float2(0.f, 0.f);
            if (!act[j]) continue;
            int mu = tops[w + 8 * j];
            float a = (kk0     <= mu) ? s0[j] : -CUDART_INF_F;
            float b = (kk0 + 1 <= mu) ? s1[j] : -CUDART_INF_F;
            float lm = fmaxf(a, b);
#pragma unroll
            for (int o = 16; o > 0; o >>= 1) lm = fmaxf(lm, __shfl_xor_sync(0xffffffffu, lm, o));
            float nm   = fmaxf(mx[j], lm);
            float corr = __expf(mx[j] - nm);
            float ea = __expf(a - nm);
            float eb = __expf(b - nm);
            float ts = ea + eb;
#pragma unroll
            for (int o = 16; o > 0; o >>= 1) ts += __shfl_xor_sync(0xffffffffu, ts, o);
            mx[j] = nm;
            l[j]  = l[j] * corr + ts;
            acc[j].x *= corr; acc[j].y *= corr;
            e2[j].x = ea; e2[j].y = eb;
        }

#pragma unroll 8
        for (int kk = 0; kk < 64; kk++) {
            float2 vv = *(const float2*)&Vs[kk][2 * lane];
#pragma unroll
            for (int j = 0; j < 6; j++) {
                if (act[j]) {
                    float ek = __shfl_sync(0xffffffffu, (kk & 1) ? e2[j].y : e2[j].x, kk >> 1);
                    acc[j].x = fmaf(ek, vv.x, acc[j].x);
                    acc[j].y = fmaf(ek, vv.y, acc[j].y);
                }
            }
        }
    }

#pragma unroll
    for (int j = 0; j < 6; j++) {
        int u = w + 8 * j;
        if (u >= UU) continue;
        int pb = (bh * UU + u) * NSPLIT + split;
        *(float2*)&g_pacc[(size_t)pb * DD + 2 * lane] = acc[j];
        if (lane == 0) { g_pm[pb] = mx[j]; g_pl[pb] = l[j]; }
    }
}

// ---------------- combine split partials into selected rows ----------------
__global__ __launch_bounds__(64) void k_comb(float* __restrict__ out)
{
    int g  = blockIdx.x;                    // bh*UU + u
    int bh = g / UU;
    int d  = threadIdx.x;
    float mg = -CUDART_INF_F;
#pragma unroll 4
    for (int i = 0; i < NSPLIT; i++) mg = fmaxf(mg, g_pm[g * NSPLIT + i]);
    float os = 0.f, ls = 0.f;
    for (int i = 0; i < NSPLIT; i++) {
        float wgt = __expf(g_pm[g * NSPLIT + i] - mg);
        ls = fmaf(wgt, g_pl[g * NSPLIT + i], ls);
        os = fmaf(wgt, g_pacc[(size_t)(g * NSPLIT + i) * DD + d], os);
    }
    int row = g_top[g];
    out[((size_t)bh * LQ + row) * DD + d] = os / ls;
}

// ---------------- cumsum(V): chunk sums (vectorized) -----------------------
// 512 threads: (r = t>>4 in 0..31, c4 = t&15). Thread sums rows r,r+32,r+64,
// r+96 of its float4 column via 4 LDG.128, then two-step smem tree.
__global__ __launch_bounds__(512) void k_csumA(const float* __restrict__ V)
{
    __shared__ __align__(16) float4 sred[32][16];   // 8 KB
    int c = blockIdx.x, bh = blockIdx.y;
    int t = threadIdx.x, r = t >> 4, c4 = t & 15;
    const float4* base = (const float4*)(V + ((size_t)bh * LQ + c * CHUNK) * DD);
    float4 a = __ldg(base + (size_t)r        * 16 + c4);
    float4 b = __ldg(base + (size_t)(r + 32) * 16 + c4);
    float4 d = __ldg(base + (size_t)(r + 64) * 16 + c4);
    float4 e = __ldg(base + (size_t)(r + 96) * 16 + c4);
    float4 s;
    s.x = (a.x + b.x) + (d.x + e.x);
    s.y = (a.y + b.y) + (d.y + e.y);
    s.z = (a.z + b.z) + (d.z + e.z);
    s.w = (a.w + b.w) + (d.w + e.w);
    sred[r][c4] = s;
    __syncthreads();
    if (t < 128) {                       // (rr = t>>4 in 0..7, c4)
        int rr = t >> 4;
        float4 p0 = sred[rr][c4],      p1 = sred[rr + 8][c4];
        float4 p2 = sred[rr + 16][c4], p3 = sred[rr + 24][c4];
        float4 q;
        q.x = (p0.x + p1.x) + (p2.x + p3.x);
        q.y = (p0.y + p1.y) + (p2.y + p3.y);
        q.z = (p0.z + p1.z) + (p2.z + p3.z);
        q.w = (p0.w + p1.w) + (p2.w + p3.w);
        sred[rr][c4] = q;
    }
    __syncthreads();
    if (t < 16) {
        float4 q0 = sred[0][t], q1 = sred[1][t], q2 = sred[2][t], q3 = sred[3][t];
        float4 q4 = sred[4][t], q5 = sred[5][t], q6 = sred[6][t], q7 = sred[7][t];
        float4 q;
        q.x = ((q0.x + q1.x) + (q2.x + q3.x)) + ((q4.x + q5.x) + (q6.x + q7.x));
        q.y = ((q0.y + q1.y) + (q2.y + q3.y)) + ((q4.y + q5.y) + (q6.y + q7.y));
        q.z = ((q0.z + q1.z) + (q2.z + q3.z)) + ((q4.z + q5.z) + (q6.z + q7.z));
        q.w = ((q0.w + q1.w) + (q2.w + q3.w)) + ((q4.w + q5.w) + (q6.w + q7.w));
        ((float4*)(g_chunk + (bh * NCHUNK + c) * DD))[t] = q;
    }
}

// ---------------- cumsum(V): per-chunk scan, register-resident -------------
// 512 threads: (g = t>>6 in 0..7, d = t&63). Thread serially scans 16 rows of
// its column in registers; cross-group offsets fixed with ONE barrier.
__global__ __launch_bounds__(512) void k_csumC(const float* __restrict__ V,
                                               float* __restrict__ out)
{
    __shared__ float gsum[8][64];
    int c = blockIdx.x, bh = blockIdx.y;
    int t = threadIdx.x, g = t >> 6, d = t & 63;

    // exclusive prefix over preceding chunk sums for this column
    float pre = 0.f;
    for (int j = 0; j < c; j++) pre += g_chunk[(bh * NCHUNK + j) * DD + d];

    const float* base = V + ((size_t)bh * LQ + c * CHUNK + g * 16) * DD + d;
    float v[16];
#pragma unroll
    for (int i = 0; i < 16; i++) v[i] = base[i * DD];
#pragma unroll
    for (int i = 1; i < 16; i++) v[i] += v[i - 1];
    gsum[g][d] = v[15];
    __syncthreads();
    float off = pre;
#pragma unroll
    for (int j = 0; j < 7; j++) if (j < g) off += gsum[j][d];
    float* ob = out + ((size_t)bh * LQ + c * CHUNK + g * 16) * DD + d;
#pragma unroll
    for (int i = 0; i < 16; i++) ob[i * DD] = v[i] + off;
}

// ---------------- launcher --------------------------------------------------
extern "C" void kernel_launch(void* const* d_in, const int* in_sizes, int n_in,
                              void* d_out, int out_size)
{
    (void)in_sizes; (void)n_in; (void)out_size;
    const float* Q   = (const float*)d_in[0];
    const float* K   = (const float*)d_in[1];
    const float* V   = (const float*)d_in[2];
    const int*   idx = (const int*)d_in[3];
    float* out = (float*)d_out;

    k_M<<<BH * LQ / 8, 256>>>(Q, K, idx);
    k_top<<<BH, 256>>>();
    k_attn<<<dim3(NSPLIT, BH), 256>>>(Q, K, V);
    k_csumA<<<dim3(NCHUNK, BH), 512>>>(V);
    k_csumC<<<dim3(NCHUNK, BH), 512>>>(V, out);
    k_comb<<<BH * UU, 64>>>(out);
}

// round 6
// speedup vs baseline: 2.1035x; 1.0907x over previous
#include <cuda_runtime.h>
#include <math_constants.h>

#define BH      16
#define LQ      4096
#define DD      64
#define SK      45
#define UU      45
#define NSPLIT  32
#define SPLIT_KEYS 128
#define NCHUNK  32
#define CHUNK   128

// ---------------- scratch (device globals; no allocation allowed) ----------
__device__ __align__(16) float g_M[BH * LQ];
__device__ __align__(16) int   g_top[BH * UU];
__device__ __align__(16) float g_pm[BH * UU * NSPLIT];
__device__ __align__(16) float g_pl[BH * UU * NSPLIT];
__device__ __align__(16) float g_pacc[BH * UU * NSPLIT * DD];
__device__ __align__(16) float g_chunk[BH * NCHUNK * DD];
__device__ int g_flag[BH * NCHUNK];

// ---------------- Stage 1: sparsity measure M ------------------------------
// One warp per (bh,q). 8 lanes per sampled key row, 4 rows per LDG step.
// Block 0 also zeroes the csum lookback flags for this launch.
__global__ __launch_bounds__(256) void k_M(const float* __restrict__ Q,
                                           const float* __restrict__ K,
                                           const int*   __restrict__ idx)
{
    __shared__ int sidx[8][48];
    int w = threadIdx.x >> 5, lane = threadIdx.x & 31;
    if (blockIdx.x == 0) {
        g_flag[threadIdx.x] = 0;
        g_flag[threadIdx.x + 256] = 0;
    }
    int gw = blockIdx.x * 8 + w;
    int bh = gw >> 12, q = gw & (LQ - 1);
    const float4* Kb4 = (const float4*)(K + (size_t)bh * (LQ * DD));

    sidx[w][lane] = idx[q * SK + lane];
    if (lane < SK - 32) sidx[w][32 + lane] = idx[q * SK + 32 + lane];
    if (lane >= 29)     sidx[w][16 + lane] = idx[q * SK + SK - 1];  // pad 45..47
    __syncwarp();

    int r = lane >> 3, c = lane & 7;   // r: row-in-group, c: float4 slot
    const float4* Qr4 = (const float4*)(Q + ((size_t)bh * LQ + q) * DD);
    float4 qa = Qr4[c];        // first half of q row
    float4 qb = Qr4[c + 8];    // second half

    float mx = -CUDART_INF_F, sm = 0.f;
#pragma unroll 4
    for (int t = 0; t < 12; t++) {
        int s = 4 * t + r;
        int row = sidx[w][s];
        const float4* kp = Kb4 + (size_t)row * 16;
        float4 ka = __ldg(kp + c);        // bytes [16c,16c+16) of half 0
        float4 kb = __ldg(kp + c + 8);    // bytes [16c,16c+16) of half 1
        float d;
        d = ka.x * qa.x;
        d = fmaf(ka.y, qa.y, d);
        d = fmaf(ka.z, qa.z, d);
        d = fmaf(ka.w, qa.w, d);
        d = fmaf(kb.x, qb.x, d);
        d = fmaf(kb.y, qb.y, d);
        d = fmaf(kb.z, qb.z, d);
        d = fmaf(kb.w, qb.w, d);
        d += __shfl_xor_sync(0xffffffffu, d, 1);
        d += __shfl_xor_sync(0xffffffffu, d, 2);
        d += __shfl_xor_sync(0xffffffffu, d, 4);
        if (s < SK) { mx = fmaxf(mx, d); sm += d; }
    }
    mx = fmaxf(mx, __shfl_xor_sync(0xffffffffu, mx, 8));
    sm +=          __shfl_xor_sync(0xffffffffu, sm, 8);
    mx = fmaxf(mx, __shfl_xor_sync(0xffffffffu, mx, 16));
    sm +=          __shfl_xor_sync(0xffffffffu, sm, 16);
    if (lane == 0) g_M[gw] = mx - sm * (1.0f / (float)LQ);
}

// ---------------- Stage 2: top-45 per (b,h), index-sorted ------------------
// Phase 1: 16 lists (8 warps x 2 half-warps of 16 lanes), each extracts its
// top-45 of 256 register-resident packed keys (value desc, index asc).
// Phase 2: rank-count merge via binary search over the 16 sorted lists.
// Phase 3: re-sort the selected 45 by index (enables banded attention skip).
__global__ __launch_bounds__(256) void k_top()
{
    __shared__ unsigned long long ckeys[16 * UU];  // 5.8 KB, sorted desc per list
    __shared__ int stop[UU];
    int bh = blockIdx.x, t = threadIdx.x, w = t >> 5, lane = t & 31;
    int h = lane >> 4, sl = lane & 15;
    int list = 2 * w + h;
    int base = w * 512 + h * 256 + sl;

    unsigned long long k[16];
#pragma unroll
    for (int kk = 0; kk < 16; kk++) {
        int i = base + 16 * kk;
        unsigned int u = __float_as_uint(g_M[bh * LQ + i]);
        u ^= (unsigned int)(((int)u >> 31)) | 0x80000000u;
        k[kk] = ((unsigned long long)u << 32) | (unsigned long long)(0xFFFFFFFFu - (unsigned int)i);
    }

    for (int it = 0; it < UU; it++) {
        unsigned long long b = k[0];
#pragma unroll
        for (int kk = 1; kk < 16; kk++) b = (k[kk] > b) ? k[kk] : b;
#pragma unroll
        for (int off = 8; off > 0; off >>= 1) {
            unsigned long long o = __shfl_xor_sync(0xffffffffu, b, off);
            b = (o > b) ? o : b;
        }
        if (sl == 0) ckeys[list * UU + it] = b;
#pragma unroll
        for (int kk = 0; kk < 16; kk++) if (k[kk] == b) k[kk] = 0ull;
    }
    __syncthreads();

    // rank-count merge: 720 candidates, rank = #candidates strictly greater
    for (int x = t; x < 16 * UU; x += 256) {
        unsigned long long Kx = ckeys[x];
        int rank = 0;
#pragma unroll
        for (int L = 0; L < 16; L++) {
            const unsigned long long* a = &ckeys[L * UU];
            int lo = 0, hi = UU;
            while (lo < hi) {
                int mid = (lo + hi) >> 1;
                if (a[mid] > Kx) lo = mid + 1; else hi = mid;
            }
            rank += lo;
        }
        if (rank < UU)
            stop[rank] = (int)(0xFFFFFFFFu - (unsigned int)(Kx & 0xFFFFFFFFull));
    }
    __syncthreads();

    // sort selected set ascending by index
    if (t < UU) {
        int my = stop[t], cnt = 0;
#pragma unroll 9
        for (int j = 0; j < UU; j++) cnt += (stop[j] < my);
        g_top[bh * UU + cnt] = my;
    }
}

// ---------------- Stage 3: split-KV flash attention for selected rows ------
// tops sorted ascending; warp owns a contiguous band of 6 sorted tops
// (band = w<4 ? w : 11-w pairs light+heavy bands on each SMSP), so whole
// warps turn inactive as kb passes their band's max top.
__global__ __launch_bounds__(256) void k_attn(const float* __restrict__ Q,
                                              const float* __restrict__ K,
                                              const float* __restrict__ V)
{
    __shared__ __align__(16) float Qs[48][DD];
    __shared__ __align__(16) float Kt[DD][66];
    __shared__ __align__(16) float Vs[64][DD];
    __shared__ int tops[UU];

    int split = blockIdx.x, bh = blockIdx.y;
    int t = threadIdx.x, w = t >> 5, lane = t & 31;
    int band = (w < 4) ? w : 11 - w;

    if (t < UU) tops[t] = g_top[bh * UU + t];
    __syncthreads();
    const float scale = 0.125f;
    for (int r = w; r < UU; r += 8) {
        float2 v = *(const float2*)(Q + ((size_t)bh * LQ + tops[r]) * DD + 2 * lane);
        Qs[r][2 * lane]     = v.x * scale;
        Qs[r][2 * lane + 1] = v.y * scale;
    }
    int s_maxtop = 0;  // tops sorted: last is max
    float mx[6], l[6]; float2 acc[6];
#pragma unroll
    for (int j = 0; j < 6; j++) { mx[j] = -CUDART_INF_F; l[j] = 0.f; acc[j] = make_float2(0.f, 0.f); }
    __syncthreads();
    s_maxtop = tops[UU - 1];

    int k0 = split * SPLIT_KEYS;
    for (int sub = 0; sub < SPLIT_KEYS / 64; sub++) {
        int kb = k0 + sub * 64;
        __syncthreads();
        if (kb > s_maxtop) break;
        for (int i = t; i < 64 * DD; i += 256) {
            int kk = i >> 6, d = i & 63;
            Kt[d][kk] = K[((size_t)bh * LQ + kb + kk) * DD + d];
            Vs[kk][d] = V[((size_t)bh * LQ + kb + kk) * DD + d];
        }
        __syncthreads();

        bool act[6]; bool any = false;
#pragma unroll
        for (int j = 0; j < 6; j++) {
            int u = 6 * band + j;
            act[j] = (u < UU) && (kb <= tops[u]);
            any |= act[j];
        }
        if (!any) continue;

        float s0[6], s1[6];
#pragma unroll
        for (int j = 0; j < 6; j++) { s0[j] = 0.f; s1[j] = 0.f; }
#pragma unroll 16
        for (int d = 0; d < DD; d++) {
            float2 kt = *(const float2*)&Kt[d][2 * lane];
#pragma unroll
            for (int j = 0; j < 6; j++) {
                if (act[j]) {
                    float qv = Qs[6 * band + j][d];
                    s0[j] = fmaf(qv, kt.x, s0[j]);
                    s1[j] = fmaf(qv, kt.y, s1[j]);
                }
            }
        }

        float2 e2[6];
        int kk0 = kb + 2 * lane;
#pragma unroll
        for (int j = 0; j < 6; j++) {
            e2[j] = make_float2(0.f, 0.f);
            if (!act[j]) continue;
            int mu = tops[6 * band + j];
            float a = (kk0     <= mu) ? s0[j] : -CUDART_INF_F;
            float b = (kk0 + 1 <= mu) ? s1[j] : -CUDART_INF_F;
            float lm = fmaxf(a, b);
#pragma unroll
            for (int o = 16; o > 0; o >>= 1) lm = fmaxf(lm, __shfl_xor_sync(0xffffffffu, lm, o));
            float nm   = fmaxf(mx[j], lm);
            float corr = __expf(mx[j] - nm);
            float ea = __expf(a - nm);
            float eb = __expf(b - nm);
            float ts = ea + eb;
#pragma unroll
            for (int o = 16; o > 0; o >>= 1) ts += __shfl_xor_sync(0xffffffffu, ts, o);
            mx[j] = nm;
            l[j]  = l[j] * corr + ts;
            acc[j].x *= corr; acc[j].y *= corr;
            e2[j].x = ea; e2[j].y = eb;
        }

#pragma unroll 8
        for (int kk = 0; kk < 64; kk++) {
            float2 vv = *(const float2*)&Vs[kk][2 * lane];
#pragma unroll
            for (int j = 0; j < 6; j++) {
                if (act[j]) {
                    float ek = __shfl_sync(0xffffffffu, (kk & 1) ? e2[j].y : e2[j].x, kk >> 1);
                    acc[j].x = fmaf(ek, vv.x, acc[j].x);
                    acc[j].y = fmaf(ek, vv.y, acc[j].y);
                }
            }
        }
    }

#pragma unroll
    for (int j = 0; j < 6; j++) {
        int u = 6 * band + j;
        if (u >= UU) continue;
        int pb = (bh * UU + u) * NSPLIT + split;
        *(float2*)&g_pacc[(size_t)pb * DD + 2 * lane] = acc[j];
        if (lane == 0) { g_pm[pb] = mx[j]; g_pl[pb] = l[j]; }
    }
}

// ---------------- combine split partials into selected rows ----------------
__global__ __launch_bounds__(64) void k_comb(float* __restrict__ out)
{
    int g  = blockIdx.x;                    // bh*UU + u
    int bh = g / UU;
    int d  = threadIdx.x;
    float mg = -CUDART_INF_F;
#pragma unroll 4
    for (int i = 0; i < NSPLIT; i++) mg = fmaxf(mg, g_pm[g * NSPLIT + i]);
    float os = 0.f, ls = 0.f;
    for (int i = 0; i < NSPLIT; i++) {
        float wgt = __expf(g_pm[g * NSPLIT + i] - mg);
        ls = fmaf(wgt, g_pl[g * NSPLIT + i], ls);
        os = fmaf(wgt, g_pacc[(size_t)(g * NSPLIT + i) * DD + d], os);
    }
    int row = g_top[g];
    out[((size_t)bh * LQ + row) * DD + d] = os / ls;
}

// ---------------- cumsum(V): single kernel with chunk-sum lookback ---------
// 512 threads: (g = t>>6 in 0..7, d = t&63). Register-serial 16-row scan,
// publish own chunk sum (fence + flag), wait on predecessor flags, combine.
// Flags are zeroed each launch by k_M block 0 (runs earlier on the stream).
__global__ __launch_bounds__(512) void k_csum(const float* __restrict__ V,
                                              float* __restrict__ out)
{
    __shared__ float gsum[8][64];
    int c = blockIdx.x, bh = blockIdx.y;
    int t = threadIdx.x, g = t >> 6, d = t & 63;

    const float* base = V + ((size_t)bh * LQ + c * CHUNK + g * 16) * DD + d;
    float v[16];
#pragma unroll
    for (int i = 0; i < 16; i++) v[i] = base[i * DD];
#pragma unroll
    for (int i = 1; i < 16; i++) v[i] += v[i - 1];
    gsum[g][d] = v[15];
    __syncthreads();

    // publish this chunk's total
    if (t < 64) {
        float tot = 0.f;
#pragma unroll
        for (int j = 0; j < 8; j++) tot += gsum[j][t];
        g_chunk[(bh * NCHUNK + c) * DD + t] = tot;
        __threadfence();
    }
    __syncthreads();
    if (t == 0) *((volatile int*)&g_flag[bh * NCHUNK + c]) = 1;

    // wait for predecessors, accumulate exclusive prefix
    float pre = 0.f;
    if (c > 0) {
        if (t < c) {
            while (*((volatile int*)&g_flag[bh * NCHUNK + t]) == 0) {}
        }
        __syncthreads();
        __threadfence();
        const float* ch = g_chunk + (size_t)bh * NCHUNK * DD + d;
        int j = 0;
        for (; j + 4 <= c; j += 4) {
            float a0 = ch[(j + 0) * DD], a1 = ch[(j + 1) * DD];
            float a2 = ch[(j + 2) * DD], a3 = ch[(j + 3) * DD];
            pre += (a0 + a1) + (a2 + a3);
        }
        for (; j < c; j++) pre += ch[j * DD];
    }

    float off = pre;
#pragma unroll
    for (int j = 0; j < 7; j++) if (j < g) off += gsum[j][d];
    float* ob = out + ((size_t)bh * LQ + c * CHUNK + g * 16) * DD + d;
#pragma unroll
    for (int i = 0; i < 16; i++) ob[i * DD] = v[i] + off;
}

// ---------------- launcher --------------------------------------------------
extern "C" void kernel_launch(void* const* d_in, const int* in_sizes, int n_in,
                              void* d_out, int out_size)
{
    (void)in_sizes; (void)n_in; (void)out_size;
    const float* Q   = (const float*)d_in[0];
    const float* K   = (const float*)d_in[1];
    const float* V   = (const float*)d_in[2];
    const int*   idx = (const int*)d_in[3];
    float* out = (float*)d_out;

    k_M<<<BH * LQ / 8, 256>>>(Q, K, idx);
    k_top<<<BH, 256>>>();
    k_attn<<<dim3(NSPLIT, BH), 256>>>(Q, K, V);
    k_csum<<<dim3(NCHUNK, BH), 512>>>(V, out);
    k_comb<<<BH * UU, 64>>>(out);
}

// round 8
// speedup vs baseline: 2.1600x; 1.0269x over previous
#include <cuda_runtime.h>
#include <math_constants.h>

#define BH      16
#define LQ      4096
#define DD      64
#define SK      45
#define UU      45
#define NSPLIT  32
#define SPLIT_KEYS 128
#define NCHUNK  32
#define CHUNK   128

// ---------------- scratch (device globals; no allocation allowed) ----------
__device__ __align__(16) float g_M[BH * LQ];
__device__ __align__(16) int   g_top[BH * UU];
__device__ __align__(16) float g_pm[BH * UU * NSPLIT];
__device__ __align__(16) float g_pl[BH * UU * NSPLIT];
__device__ __align__(16) float g_pacc[BH * UU * NSPLIT * DD];
__device__ __align__(16) float g_chunk[BH * NCHUNK * DD];

// ---------------- Stage 1: sparsity measure M ------------------------------
// One warp per (bh,q). 8 lanes per sampled key row, 4 rows per LDG step.
// Software pipeline depth 16 LDGs: preload iters 0-7, then compute-4/load-4.
__global__ __launch_bounds__(256) void k_M(const float* __restrict__ Q,
                                           const float* __restrict__ K,
                                           const int*   __restrict__ idx)
{
    __shared__ int sidx[8][48];
    int w = threadIdx.x >> 5, lane = threadIdx.x & 31;
    int gw = blockIdx.x * 8 + w;
    int bh = gw >> 12, q = gw & (LQ - 1);
    const float4* Kb4 = (const float4*)(K + (size_t)bh * (LQ * DD));

    sidx[w][lane] = idx[q * SK + lane];
    if (lane < SK - 32) sidx[w][32 + lane] = idx[q * SK + 32 + lane];
    if (lane >= 29)     sidx[w][16 + lane] = idx[q * SK + SK - 1];  // pad 45..47
    __syncwarp();

    int r = lane >> 3, c = lane & 7;   // r: row-in-group, c: float4 slot
    const float4* Qr4 = (const float4*)(Q + ((size_t)bh * LQ + q) * DD);
    float4 qa = Qr4[c];        // first half of q row
    float4 qb = Qr4[c + 8];    // second half

    float4 A0[4], B0[4], A1[4], B1[4];
    float mx = -CUDART_INF_F, sm = 0.f;

#pragma unroll
    for (int i = 0; i < 4; i++) {                       // iters 0-3
        const float4* kp = Kb4 + (size_t)sidx[w][4 * i + r] * 16;
        A0[i] = __ldg(kp + c); B0[i] = __ldg(kp + c + 8);
    }
#pragma unroll
    for (int i = 0; i < 4; i++) {                       // iters 4-7
        const float4* kp = Kb4 + (size_t)sidx[w][16 + 4 * i + r] * 16;
        A1[i] = __ldg(kp + c); B1[i] = __ldg(kp + c + 8);
    }

#pragma unroll
    for (int blk = 0; blk < 3; blk++) {
        // consume buffer A0/B0 (iters 4*blk .. 4*blk+3)
#pragma unroll
        for (int i = 0; i < 4; i++) {
            float4 ka = A0[i], kb = B0[i];
            float d;
            d = ka.x * qa.x;
            d = fmaf(ka.y, qa.y, d);
            d = fmaf(ka.z, qa.z, d);
            d = fmaf(ka.w, qa.w, d);
            d = fmaf(kb.x, qb.x, d);
            d = fmaf(kb.y, qb.y, d);
            d = fmaf(kb.z, qb.z, d);
            d = fmaf(kb.w, qb.w, d);
            d += __shfl_xor_sync(0xffffffffu, d, 1);
            d += __shfl_xor_sync(0xffffffffu, d, 2);
            d += __shfl_xor_sync(0xffffffffu, d, 4);
            int samp = 16 * blk + 4 * i + r;
            if (samp < SK) { mx = fmaxf(mx, d); sm += d; }
        }
        // rotate: A1 -> A0, and prefetch next block into A1 (if any)
#pragma unroll
        for (int i = 0; i < 4; i++) { A0[i] = A1[i]; B0[i] = B1[i]; }
        if (blk == 0) {
#pragma unroll
            for (int i = 0; i < 4; i++) {               // iters 8-11
                const float4* kp = Kb4 + (size_t)sidx[w][32 + 4 * i + r] * 16;
                A1[i] = __ldg(kp + c); B1[i] = __ldg(kp + c + 8);
            }
        }
    }

    mx = fmaxf(mx, __shfl_xor_sync(0xffffffffu, mx, 8));
    sm +=          __shfl_xor_sync(0xffffffffu, sm, 8);
    mx = fmaxf(mx, __shfl_xor_sync(0xffffffffu, mx, 16));
    sm +=          __shfl_xor_sync(0xffffffffu, sm, 16);
    if (lane == 0) g_M[gw] = mx - sm * (1.0f / (float)LQ);
}

// ---------------- Stage 2: top-45 per (b,h), index-sorted ------------------
__global__ __launch_bounds__(256) void k_top()
{
    __shared__ unsigned long long ckeys[16 * UU];
    __shared__ int stop[UU];
    int bh = blockIdx.x, t = threadIdx.x, w = t >> 5, lane = t & 31;
    int h = lane >> 4, sl = lane & 15;
    int list = 2 * w + h;
    int base = w * 512 + h * 256 + sl;

    unsigned long long k[16];
#pragma unroll
    for (int kk = 0; kk < 16; kk++) {
        int i = base + 16 * kk;
        unsigned int u = __float_as_uint(g_M[bh * LQ + i]);
        u ^= (unsigned int)(((int)u >> 31)) | 0x80000000u;
        k[kk] = ((unsigned long long)u << 32) | (unsigned long long)(0xFFFFFFFFu - (unsigned int)i);
    }

    for (int it = 0; it < UU; it++) {
        unsigned long long b = k[0];
#pragma unroll
        for (int kk = 1; kk < 16; kk++) b = (k[kk] > b) ? k[kk] : b;
#pragma unroll
        for (int off = 8; off > 0; off >>= 1) {
            unsigned long long o = __shfl_xor_sync(0xffffffffu, b, off);
            b = (o > b) ? o : b;
        }
        if (sl == 0) ckeys[list * UU + it] = b;
#pragma unroll
        for (int kk = 0; kk < 16; kk++) if (k[kk] == b) k[kk] = 0ull;
    }
    __syncthreads();

    for (int x = t; x < 16 * UU; x += 256) {
        unsigned long long Kx = ckeys[x];
        int rank = 0;
#pragma unroll
        for (int L = 0; L < 16; L++) {
            const unsigned long long* a = &ckeys[L * UU];
            int lo = 0, hi = UU;
            while (lo < hi) {
                int mid = (lo + hi) >> 1;
                if (a[mid] > Kx) lo = mid + 1; else hi = mid;
            }
            rank += lo;
        }
        if (rank < UU)
            stop[rank] = (int)(0xFFFFFFFFu - (unsigned int)(Kx & 0xFFFFFFFFull));
    }
    __syncthreads();

    if (t < UU) {
        int my = stop[t], cnt = 0;
#pragma unroll 9
        for (int j = 0; j < UU; j++) cnt += (stop[j] < my);
        g_top[bh * UU + cnt] = my;
    }
}

// ---------------- Stage 3: split-KV flash attention for selected rows ------
__global__ __launch_bounds__(256) void k_attn(const float* __restrict__ Q,
                                              const float* __restrict__ K,
                                              const float* __restrict__ V)
{
    __shared__ __align__(16) float Qs[48][DD];
    __shared__ __align__(16) float Kt[DD][66];
    __shared__ __align__(16) float Vs[64][DD];
    __shared__ int tops[UU];

    int split = blockIdx.x, bh = blockIdx.y;
    int t = threadIdx.x, w = t >> 5, lane = t & 31;
    int band = (w < 4) ? w : 11 - w;

    if (t < UU) tops[t] = g_top[bh * UU + t];
    __syncthreads();
    const float scale = 0.125f;
    for (int r = w; r < UU; r += 8) {
        float2 v = *(const float2*)(Q + ((size_t)bh * LQ + tops[r]) * DD + 2 * lane);
        Qs[r][2 * lane]     = v.x * scale;
        Qs[r][2 * lane + 1] = v.y * scale;
    }
    int s_maxtop = 0;
    float mx[6], l[6]; float2 acc[6];
#pragma unroll
    for (int j = 0; j < 6; j++) { mx[j] = -CUDART_INF_F; l[j] = 0.f; acc[j] = make_float2(0.f, 0.f); }
    __syncthreads();
    s_maxtop = tops[UU - 1];

    int k0 = split * SPLIT_KEYS;
    for (int sub = 0; sub < SPLIT_KEYS / 64; sub++) {
        int kb = k0 + sub * 64;
        __syncthreads();
        if (kb > s_maxtop) break;
        for (int i = t; i < 64 * DD; i += 256) {
            int kk = i >> 6, d = i & 63;
            Kt[d][kk] = K[((size_t)bh * LQ + kb + kk) * DD + d];
            Vs[kk][d] = V[((size_t)bh * LQ + kb + kk) * DD + d];
        }
        __syncthreads();

        bool act[6]; bool any = false;
#pragma unroll
        for (int j = 0; j < 6; j++) {
            int u = 6 * band + j;
            act[j] = (u < UU) && (kb <= tops[u]);
            any |= act[j];
        }
        if (!any) continue;

        float s0[6], s1[6];
#pragma unroll
        for (int j = 0; j < 6; j++) { s0[j] = 0.f; s1[j] = 0.f; }
#pragma unroll 16
        for (int d = 0; d < DD; d++) {
            float2 kt = *(const float2*)&Kt[d][2 * lane];
#pragma unroll
            for (int j = 0; j < 6; j++) {
                if (act[j]) {
                    float qv = Qs[6 * band + j][d];
                    s0[j] = fmaf(qv, kt.x, s0[j]);
                    s1[j] = fmaf(qv, kt.y, s1[j]);
                }
            }
        }

        float2 e2[6];
        int kk0 = kb + 2 * lane;
#pragma unroll
        for (int j = 0; j < 6; j++) {
            e2[j] = make_float2(0.f, 0.f);
            if (!act[j]) continue;
            int mu = tops[6 * band + j];
            float a = (kk0     <= mu) ? s0[j] : -CUDART_INF_F;
            float b = (kk0 + 1 <= mu) ? s1[j] : -CUDART_INF_F;
            float lm = fmaxf(a, b);
#pragma unroll
            for (int o = 16; o > 0; o >>= 1) lm = fmaxf(lm, __shfl_xor_sync(0xffffffffu, lm, o));
            float nm   = fmaxf(mx[j], lm);
            float corr = __expf(mx[j] - nm);
            float ea = __expf(a - nm);
            float eb = __expf(b - nm);
            float ts = ea + eb;
#pragma unroll
            for (int o = 16; o > 0; o >>= 1) ts += __shfl_xor_sync(0xffffffffu, ts, o);
            mx[j] = nm;
            l[j]  = l[j] * corr + ts;
            acc[j].x *= corr; acc[j].y *= corr;
            e2[j].x = ea; e2[j].y = eb;
        }

#pragma unroll 8
        for (int kk = 0; kk < 64; kk++) {
            float2 vv = *(const float2*)&Vs[kk][2 * lane];
#pragma unroll
            for (int j = 0; j < 6; j++) {
                if (act[j]) {
                    float ek = __shfl_sync(0xffffffffu, (kk & 1) ? e2[j].y : e2[j].x, kk >> 1);
                    acc[j].x = fmaf(ek, vv.x, acc[j].x);
                    acc[j].y = fmaf(ek, vv.y, acc[j].y);
                }
            }
        }
    }

#pragma unroll
    for (int j = 0; j < 6; j++) {
        int u = 6 * band + j;
        if (u >= UU) continue;
        int pb = (bh * UU + u) * NSPLIT + split;
        *(float2*)&g_pacc[(size_t)pb * DD + 2 * lane] = acc[j];
        if (lane == 0) { g_pm[pb] = mx[j]; g_pl[pb] = l[j]; }
    }
}

// ---------------- combine split partials into selected rows ----------------
__global__ __launch_bounds__(64) void k_comb(float* __restrict__ out)
{
    int g  = blockIdx.x;                    // bh*UU + u
    int bh = g / UU;
    int d  = threadIdx.x;
    float mg = -CUDART_INF_F;
#pragma unroll 4
    for (int i = 0; i < NSPLIT; i++) mg = fmaxf(mg, g_pm[g * NSPLIT + i]);
    float os = 0.f, ls = 0.f;
    for (int i = 0; i < NSPLIT; i++) {
        float wgt = __expf(g_pm[g * NSPLIT + i] - mg);
        ls = fmaf(wgt, g_pl[g * NSPLIT + i], ls);
        os = fmaf(wgt, g_pacc[(size_t)(g * NSPLIT + i) * DD + d], os);
    }
    int row = g_top[g];
    out[((size_t)bh * LQ + row) * DD + d] = os / ls;
}

// ---------------- cumsum(V): chunk sums (vectorized) -----------------------
__global__ __launch_bounds__(512) void k_csumA(const float* __restrict__ V)
{
    __shared__ __align__(16) float4 sred[32][16];   // 8 KB
    int c = blockIdx.x, bh = blockIdx.y;
    int t = threadIdx.x, r = t >> 4, c4 = t & 15;
    const float4* base = (const float4*)(V + ((size_t)bh * LQ + c * CHUNK) * DD);
    float4 a = __ldg(base + (size_t)r        * 16 + c4);
    float4 b = __ldg(base + (size_t)(r + 32) * 16 + c4);
    float4 d = __ldg(base + (size_t)(r + 64) * 16 + c4);
    float4 e = __ldg(base + (size_t)(r + 96) * 16 + c4);
    float4 s;
    s.x = (a.x + b.x) + (d.x + e.x);
    s.y = (a.y + b.y) + (d.y + e.y);
    s.z = (a.z + b.z) + (d.z + e.z);
    s.w = (a.w + b.w) + (d.w + e.w);
    sred[r][c4] = s;
    __syncthreads();
    if (t < 128) {
        int rr = t >> 4;
        float4 p0 = sred[rr][c4],      p1 = sred[rr + 8][c4];
        float4 p2 = sred[rr + 16][c4], p3 = sred[rr + 24][c4];
        float4 q;
        q.x = (p0.x + p1.x) + (p2.x + p3.x);
        q.y = (p0.y + p1.y) + (p2.y + p3.y);
        q.z = (p0.z + p1.z) + (p2.z + p3.z);
        q.w = (p0.w + p1.w) + (p2.w + p3.w);
        sred[rr][c4] = q;
    }
    __syncthreads();
    if (t < 16) {
        float4 q0 = sred[0][t], q1 = sred[1][t], q2 = sred[2][t], q3 = sred[3][t];
        float4 q4 = sred[4][t], q5 = sred[5][t], q6 = sred[6][t], q7 = sred[7][t];
        float4 q;
        q.x = ((q0.x + q1.x) + (q2.x + q3.x)) + ((q4.x + q5.x) + (q6.x + q7.x));
        q.y = ((q0.y + q1.y) + (q2.y + q3.y)) + ((q4.y + q5.y) + (q6.y + q7.y));
        q.z = ((q0.z + q1.z) + (q2.z + q3.z)) + ((q4.z + q5.z) + (q6.z + q7.z));
        q.w = ((q0.w + q1.w) + (q2.w + q3.w)) + ((q4.w + q5.w) + (q6.w + q7.w));
        ((float4*)(g_chunk + (bh * NCHUNK + c) * DD))[t] = q;
    }
}

// ---------------- cumsum(V): per-chunk scan, register-resident -------------
__global__ __launch_bounds__(512) void k_csumC(const float* __restrict__ V,
                                               float* __restrict__ out)
{
    __shared__ float gsum[8][64];
    int c = blockIdx.x, bh = blockIdx.y;
    int t = threadIdx.x, g = t >> 6, d = t & 63;

    float pre = 0.f;
    for (int j = 0; j < c; j++) pre += g_chunk[(bh * NCHUNK + j) * DD + d];

    const float* base = V + ((size_t)bh * LQ + c * CHUNK + g * 16) * DD + d;
    float v[16];
#pragma unroll
    for (int i = 0; i < 16; i++) v[i] = base[i * DD];
#pragma unroll
    for (int i = 1; i < 16; i++) v[i] += v[i - 1];
    gsum[g][d] = v[15];
    __syncthreads();
    float off = pre;
#pragma unroll
    for (int j = 0; j < 7; j++) if (j < g) off += gsum[j][d];
    float* ob = out + ((size_t)bh * LQ + c * CHUNK + g * 16) * DD + d;
#pragma unroll
    for (int i = 0; i < 16; i++) ob[i * DD] = v[i] + off;
}

// ---------------- launcher --------------------------------------------------
extern "C" void kernel_launch(void* const* d_in, const int* in_sizes, int n_in,
                              void* d_out, int out_size)
{
    (void)in_sizes; (void)n_in; (void)out_size;
    const float* Q   = (const float*)d_in[0];
    const float* K   = (const float*)d_in[1];
    const float* V   = (const float*)d_in[2];
    const int*   idx = (const int*)d_in[3];
    float* out = (float*)d_out;

    k_M<<<BH * LQ / 8, 256>>>(Q, K, idx);
    k_top<<<BH, 256>>>();
    k_attn<<<dim3(NSPLIT, BH), 256>>>(Q, K, V);
    k_csumA<<<dim3(NCHUNK, BH), 512>>>(V);
    k_csumC<<<dim3(NCHUNK, BH), 512>>>(V, out);
    k_comb<<<BH * UU, 64>>>(out);
}